// round 9
// baseline (speedup 1.0000x reference)
#include <cuda_runtime.h>
#include <cuda_bf16.h>
#include <cstdint>

// Problem constants
#define SS   96
#define BB   16
#define DD   512
#define HIDN 128
#define NR   (SS * BB)   // 1536 rows

// Intermediate activations
__device__ float g_ha[NR * HIDN];      // ha + b1
__device__ float g_hb[NR * HIDN];

// ---------------------------------------------------------------------------
// Helpers
// ---------------------------------------------------------------------------
__device__ __forceinline__ unsigned smem_u32(const void* p)
{
    unsigned a;
    asm("{ .reg .u64 t; cvta.to.shared.u64 t, %1; cvt.u32.u64 %0, t; }"
        : "=r"(a) : "l"(p));
    return a;
}

// SW128 swizzle (Swizzle<3,4,3>)
__device__ __forceinline__ unsigned sw128(unsigned byte_off)
{
    return byte_off ^ ((byte_off >> 3) & 0x70);
}

// Split a float4 into bf16 hi (round-nearest) and bf16 lo (residual).
__device__ __forceinline__ void cvt_split(float4 v, uint2& hw, uint2& lw)
{
    __nv_bfloat162 h01 = __float22bfloat162_rn(make_float2(v.x, v.y));
    __nv_bfloat162 h23 = __float22bfloat162_rn(make_float2(v.z, v.w));
    float2 hf01 = __bfloat1622float2(h01);
    float2 hf23 = __bfloat1622float2(h23);
    __nv_bfloat162 l01 = __float22bfloat162_rn(
        make_float2(v.x - hf01.x, v.y - hf01.y));
    __nv_bfloat162 l23 = __float22bfloat162_rn(
        make_float2(v.z - hf23.x, v.w - hf23.y));
    hw.x = *reinterpret_cast<unsigned*>(&h01);
    hw.y = *reinterpret_cast<unsigned*>(&h23);
    lw.x = *reinterpret_cast<unsigned*>(&l01);
    lw.y = *reinterpret_cast<unsigned*>(&l23);
}

__device__ __forceinline__ void ldsm_x4(
    uint32_t& r0, uint32_t& r1, uint32_t& r2, uint32_t& r3, unsigned addr)
{
    asm volatile("ldmatrix.sync.aligned.m8n8.x4.shared.b16 {%0,%1,%2,%3}, [%4];"
                 : "=r"(r0), "=r"(r1), "=r"(r2), "=r"(r3) : "r"(addr));
}

__device__ __forceinline__ void mma_bf16(
    float* d, uint32_t a0, uint32_t a1, uint32_t a2, uint32_t a3,
    uint32_t b0, uint32_t b1)
{
    asm volatile(
        "mma.sync.aligned.m16n8k16.row.col.f32.bf16.bf16.f32 "
        "{%0,%1,%2,%3}, {%4,%5,%6,%7}, {%8,%9}, {%0,%1,%2,%3};"
        : "+f"(d[0]), "+f"(d[1]), "+f"(d[2]), "+f"(d[3])
        : "r"(a0), "r"(a1), "r"(a2), "r"(a3), "r"(b0), "r"(b1));
}

// Packed f32x2 ops (stage2)
__device__ __forceinline__ unsigned long long add2(
    unsigned long long a, unsigned long long b)
{
    unsigned long long d;
    asm("add.rn.f32x2 %0, %1, %2;" : "=l"(d) : "l"(a), "l"(b));
    return d;
}
__device__ __forceinline__ unsigned long long ffma2(
    unsigned long long a, unsigned long long b, unsigned long long c)
{
    unsigned long long d;
    asm("fma.rn.f32x2 %0, %1, %2, %3;" : "=l"(d) : "l"(a), "l"(b), "l"(c));
    return d;
}
__device__ __forceinline__ unsigned long long relu2(unsigned long long x)
{
    unsigned long long r;
    asm("{\n\t.reg .f32 lo, hi;\n\t"
        "mov.b64 {lo, hi}, %1;\n\t"
        "max.f32 lo, lo, 0f00000000;\n\t"
        "max.f32 hi, hi, 0f00000000;\n\t"
        "mov.b64 %0, {lo, hi};\n\t}"
        : "=l"(r) : "l"(x));
    return r;
}
__device__ __forceinline__ float2 unpk2(unsigned long long v)
{
    float2 f;
    asm("mov.b64 {%0, %1}, %2;" : "=f"(f.x), "=f"(f.y) : "l"(v));
    return f;
}

// ---------------------------------------------------------------------------
// Stage 1: bf16-split GEMM on mma.sync m16n8k16. 256 threads.
//   C[r][h] = sum_k X[r][k] * W[h][k];  D += Ahi*Bhi + Ahi*Blo + Alo*Bhi.
// Block tile M=32, N=64; 8 warps = 2(m) x 4(n); warp tile 16x16.
// K chunked by 64 (one SW128 atom row), double-buffered, ONE sync per chunk:
//   LDG(t+1) -> MMA(t) -> cvt+STS(t+1 into other buffer) -> sync.
// Grid (48, 2, 2) = 192 blocks.
// ---------------------------------------------------------------------------
#define AHI_OFF   0
#define ALO_OFF   4096
#define BHI_OFF   8192
#define BLO_OFF   16384
#define BUF_BYTES 24576
#define S1_SMEM   (2 * BUF_BYTES)   // 49152

__global__ __launch_bounds__(256) void stage1_kernel(
    const float* __restrict__ X0, const float* __restrict__ X1,
    const float* __restrict__ W1, const float* __restrict__ b1)
{
    extern __shared__ char smem[];
    const unsigned sbase = smem_u32(smem);

    const int mt = blockIdx.x;   // 0..47
    const int nt = blockIdx.y;   // 0..1
    const int z  = blockIdx.z;   // 0..1
    const int m0 = mt * 32;
    const int n0 = nt * 64;

    const float* __restrict__ X = z ? X1 : X0;
    const float* __restrict__ W = W1 + (size_t)z * DD;   // row stride 2*DD
    float* __restrict__ C = z ? g_hb : g_ha;

    const int tid  = threadIdx.x;
    const int wid  = tid >> 5;
    const int lane = tid & 31;
    const int wm   = wid & 1;    // m offset wm*16
    const int wn   = wid >> 1;   // n offset wn*16

    // Fill coords: A tile 32x64 = 512 float4 -> 2/thread;
    //              B tile 64x64 = 1024 float4 -> 4/thread.
    int arow[2], aq[2], brow[4], bq[4];
    #pragma unroll
    for (int i = 0; i < 2; i++) {
        const int flat = tid + i * 256;
        arow[i] = flat >> 4;  aq[i] = flat & 15;
    }
    #pragma unroll
    for (int i = 0; i < 4; i++) {
        const int flat = tid + i * 256;
        brow[i] = flat >> 4;  bq[i] = flat & 15;
    }

    // ldmatrix lane addressing
    const int a_r  = (lane & 15);
    const int a_ch = (lane >> 4);           // 0..1
    const int b_n  = (lane & 7) + ((lane >> 4) << 3);
    const int b_ch = (lane >> 3) & 1;

    float4 rA[2], rB[4];

    // ---- prologue: LDG chunk 0, cvt+STS into buf 0, sync ----
    #pragma unroll
    for (int i = 0; i < 2; i++)
        rA[i] = *reinterpret_cast<const float4*>(
            &X[(size_t)(m0 + arow[i]) * DD + aq[i] * 4]);
    #pragma unroll
    for (int i = 0; i < 4; i++)
        rB[i] = *reinterpret_cast<const float4*>(
            &W[(size_t)(n0 + brow[i]) * (2 * DD) + bq[i] * 4]);

    #pragma unroll
    for (int i = 0; i < 2; i++) {
        const unsigned so = sw128((unsigned)(arow[i] * 128 + aq[i] * 8));
        uint2 hw, lw;
        cvt_split(rA[i], hw, lw);
        *reinterpret_cast<uint2*>(smem + AHI_OFF + so) = hw;
        *reinterpret_cast<uint2*>(smem + ALO_OFF + so) = lw;
    }
    #pragma unroll
    for (int i = 0; i < 4; i++) {
        const unsigned so = sw128((unsigned)(brow[i] * 128 + bq[i] * 8));
        uint2 hw, lw;
        cvt_split(rB[i], hw, lw);
        *reinterpret_cast<uint2*>(smem + BHI_OFF + so) = hw;
        *reinterpret_cast<uint2*>(smem + BLO_OFF + so) = lw;
    }
    __syncthreads();

    float acc[2][4];
    #pragma unroll
    for (int ni = 0; ni < 2; ni++)
        #pragma unroll
        for (int r = 0; r < 4; r++) acc[ni][r] = 0.0f;

    #pragma unroll 1
    for (int t = 0; t < 8; t++) {
        const unsigned bufOff = (unsigned)((t & 1) * BUF_BYTES);

        // ---- LDG for chunk t+1 (latency hidden behind MMAs below) ----
        if (t < 7) {
            const int k0 = (t + 1) * 64;
            #pragma unroll
            for (int i = 0; i < 2; i++)
                rA[i] = *reinterpret_cast<const float4*>(
                    &X[(size_t)(m0 + arow[i]) * DD + k0 + aq[i] * 4]);
            #pragma unroll
            for (int i = 0; i < 4; i++)
                rB[i] = *reinterpret_cast<const float4*>(
                    &W[(size_t)(n0 + brow[i]) * (2 * DD) + k0 + bq[i] * 4]);
        }

        // ---- MMAs on buffer t ----
        const unsigned aHi = sbase + bufOff + AHI_OFF;
        const unsigned aLo = sbase + bufOff + ALO_OFF;
        const unsigned bHi = sbase + bufOff + BHI_OFF;
        const unsigned bLo = sbase + bufOff + BLO_OFF;

        #pragma unroll
        for (int ks = 0; ks < 4; ks++) {
            const unsigned kb = (unsigned)(ks * 32);

            uint32_t ah[4], al[4];
            {
                const unsigned off = sw128(
                    (unsigned)((wm * 16 + a_r) * 128) + kb + a_ch * 16);
                ldsm_x4(ah[0], ah[1], ah[2], ah[3], aHi + off);
                ldsm_x4(al[0], al[1], al[2], al[3], aLo + off);
            }
            uint32_t bh[4], bl[4];
            {
                const unsigned off = sw128(
                    (unsigned)((wn * 16 + b_n) * 128) + kb + b_ch * 16);
                ldsm_x4(bh[0], bh[1], bh[2], bh[3], bHi + off);
                ldsm_x4(bl[0], bl[1], bl[2], bl[3], bLo + off);
            }

            #pragma unroll
            for (int ni = 0; ni < 2; ni++) {
                mma_bf16(acc[ni], ah[0], ah[1], ah[2], ah[3],
                         bh[2 * ni], bh[2 * ni + 1]);
                mma_bf16(acc[ni], ah[0], ah[1], ah[2], ah[3],
                         bl[2 * ni], bl[2 * ni + 1]);
                mma_bf16(acc[ni], al[0], al[1], al[2], al[3],
                         bh[2 * ni], bh[2 * ni + 1]);
            }
        }

        // ---- cvt + STS chunk t+1 into the OTHER buffer, then one sync ----
        if (t < 7) {
            const unsigned nbuf = (unsigned)(((t + 1) & 1) * BUF_BYTES);
            #pragma unroll
            for (int i = 0; i < 2; i++) {
                const unsigned so = sw128((unsigned)(arow[i] * 128 + aq[i] * 8));
                uint2 hw, lw;
                cvt_split(rA[i], hw, lw);
                *reinterpret_cast<uint2*>(smem + nbuf + AHI_OFF + so) = hw;
                *reinterpret_cast<uint2*>(smem + nbuf + ALO_OFF + so) = lw;
            }
            #pragma unroll
            for (int i = 0; i < 4; i++) {
                const unsigned so = sw128((unsigned)(brow[i] * 128 + bq[i] * 8));
                uint2 hw, lw;
                cvt_split(rB[i], hw, lw);
                *reinterpret_cast<uint2*>(smem + nbuf + BHI_OFF + so) = hw;
                *reinterpret_cast<uint2*>(smem + nbuf + BLO_OFF + so) = lw;
            }
            __syncthreads();
        }
    }

    // ---- Epilogue: write D fragments (+ b1 for z=0) ----
    #pragma unroll
    for (int ni = 0; ni < 2; ni++) {
        const int row = m0 + wm * 16 + (lane >> 2);
        const int col = n0 + wn * 16 + ni * 8 + (lane & 3) * 2;
        float2 bias = make_float2(0.f, 0.f);
        if (z == 0)
            bias = *reinterpret_cast<const float2*>(&b1[col]);
        float2 o0, o1;
        o0.x = acc[ni][0] + bias.x;
        o0.y = acc[ni][1] + bias.y;
        o1.x = acc[ni][2] + bias.x;
        o1.y = acc[ni][3] + bias.y;
        *reinterpret_cast<float2*>(&C[(size_t)row * HIDN + col]) = o0;
        *reinterpret_cast<float2*>(&C[(size_t)(row + 8) * HIDN + col]) = o1;
    }
}

// ---------------------------------------------------------------------------
// Stage 2: out[i,j,b,c] = sum_h relu(ha'[i,b,h]+hb[j,b,h])*W2[c,h]+b2[c]
// Grid (6,3,16) = 768... actually (6,3,16) = 288 blocks: 16x32 (i,j) tile
// at fixed b, 256 threads, 1x2 pairs per thread. Packed f32x2 along h with
// (even-h, odd-h) split accumulators; horizontal add at the end.
// ---------------------------------------------------------------------------
#define TI 16
#define TJ 32
#define PADH 132  // 128+4 floats, rows 16B aligned

__global__ __launch_bounds__(256) void stage2_kernel(
    const float* __restrict__ W2, const float* __restrict__ b2,
    float* __restrict__ out)
{
    __shared__ float sA[TI][PADH];
    __shared__ float sB[TJ][PADH];
    __shared__ float sW2[2 * HIDN];

    const int i0  = blockIdx.x * TI;
    const int j0  = blockIdx.y * TJ;
    const int b   = blockIdx.z;
    const int tid = threadIdx.x;

    #pragma unroll
    for (int p = 0; p < 2; p++) {
        const int q   = tid + p * 256;  // 0..511
        const int row = q >> 5;         // 0..15
        const int hq  = q & 31;
        float4 va = *reinterpret_cast<const float4*>(
            &g_ha[((size_t)(i0 + row) * BB + b) * HIDN + hq * 4]);
        *reinterpret_cast<float4*>(&sA[row][hq * 4]) = va;
    }
    #pragma unroll
    for (int p = 0; p < 4; p++) {
        const int q   = tid + p * 256;  // 0..1023
        const int row = q >> 5;         // 0..31
        const int hq  = q & 31;
        float4 vb = *reinterpret_cast<const float4*>(
            &g_hb[((size_t)(j0 + row) * BB + b) * HIDN + hq * 4]);
        *reinterpret_cast<float4*>(&sB[row][hq * 4]) = vb;
    }
    if (tid < 64) {
        float4 w = *reinterpret_cast<const float4*>(&W2[tid * 4]);
        *reinterpret_cast<float4*>(&sW2[tid * 4]) = w;
    }
    __syncthreads();

    const int rg = tid >> 4;   // 0..15 -> i row
    const int cg = tid & 15;   // 0..15 -> j cols cg, cg+16

    // acc[jj][c]: packed (even-h, odd-h) partials for channel c
    unsigned long long acc[2][2];
    #pragma unroll
    for (int jj = 0; jj < 2; jj++) { acc[jj][0] = 0ull; acc[jj][1] = 0ull; }

    #pragma unroll
    for (int hq = 0; hq < HIDN / 4; hq++) {
        ulonglong2 a  = *reinterpret_cast<const ulonglong2*>(&sA[rg][hq * 4]);
        ulonglong2 q0 = *reinterpret_cast<const ulonglong2*>(&sB[cg][hq * 4]);
        ulonglong2 q1 = *reinterpret_cast<const ulonglong2*>(&sB[cg + 16][hq * 4]);
        ulonglong2 w0 = *reinterpret_cast<const ulonglong2*>(&sW2[hq * 4]);
        ulonglong2 w1 = *reinterpret_cast<const ulonglong2*>(&sW2[HIDN + hq * 4]);

        const unsigned long long av[2] = {a.x, a.y};
        const unsigned long long qv[2][2] = {{q0.x, q0.y}, {q1.x, q1.y}};
        const unsigned long long wv[2][2] = {{w0.x, w0.y}, {w1.x, w1.y}};

        #pragma unroll
        for (int hp = 0; hp < 2; hp++) {
            #pragma unroll
            for (int jj = 0; jj < 2; jj++) {
                unsigned long long v = relu2(add2(av[hp], qv[jj][hp]));
                acc[jj][0] = ffma2(v, wv[0][hp], acc[jj][0]);
                acc[jj][1] = ffma2(v, wv[1][hp], acc[jj][1]);
            }
        }
    }

    const float bb0 = b2[0];
    const float bb1 = b2[1];
    #pragma unroll
    for (int jj = 0; jj < 2; jj++) {
        const int i = i0 + rg;
        const int j = j0 + cg + jj * 16;
        const size_t idx = (((size_t)i * SS + j) * BB + b) * 2;
        float2 p0 = unpk2(acc[jj][0]);
        float2 p1 = unpk2(acc[jj][1]);
        float2 o;
        o.x = p0.x + p0.y + bb0;
        o.y = p1.x + p1.y + bb1;
        *reinterpret_cast<float2*>(&out[idx]) = o;
    }
}

// ---------------------------------------------------------------------------
// Inputs: embeds, umask, qmask, embeds_cmp, W1, b1, W2, b2
// ---------------------------------------------------------------------------
extern "C" void kernel_launch(void* const* d_in, const int* in_sizes, int n_in,
                              void* d_out, int out_size)
{
    const float* embeds     = (const float*)d_in[0];
    const float* embeds_cmp = (const float*)d_in[3];
    const float* W1         = (const float*)d_in[4];
    const float* b1         = (const float*)d_in[5];
    const float* W2         = (const float*)d_in[6];
    const float* b2         = (const float*)d_in[7];
    float* out = (float*)d_out;

    cudaFuncSetAttribute(stage1_kernel,
                         cudaFuncAttributeMaxDynamicSharedMemorySize, S1_SMEM);

    stage1_kernel<<<dim3(48, 2, 2), 256, S1_SMEM>>>(embeds, embeds_cmp, W1, b1);
    stage2_kernel<<<dim3(6, 3, 16), 256>>>(W2, b2, out);
}

// round 10
// speedup vs baseline: 1.2453x; 1.2453x over previous
#include <cuda_runtime.h>
#include <cuda_fp16.h>
#include <cstdint>

// Problem constants
#define SS   96
#define BB   16
#define DD   512
#define HIDN 128
#define NR   (SS * BB)   // 1536 rows

// Intermediate activations
__device__ float g_ha[NR * HIDN];      // ha + b1
__device__ float g_hb[NR * HIDN];

// ---------------------------------------------------------------------------
// Helpers
// ---------------------------------------------------------------------------
__device__ __forceinline__ unsigned smem_u32(const void* p)
{
    unsigned a;
    asm("{ .reg .u64 t; cvta.to.shared.u64 t, %1; cvt.u32.u64 %0, t; }"
        : "=r"(a) : "l"(p));
    return a;
}

// SW128 swizzle (Swizzle<3,4,3>)
__device__ __forceinline__ unsigned sw128(unsigned byte_off)
{
    return byte_off ^ ((byte_off >> 3) & 0x70);
}

// Convert float4 -> 4 fp16 packed in uint2
__device__ __forceinline__ uint2 cvt_h4(float4 v)
{
    __half2 h01 = __float22half2_rn(make_float2(v.x, v.y));
    __half2 h23 = __float22half2_rn(make_float2(v.z, v.w));
    uint2 r;
    r.x = *reinterpret_cast<unsigned*>(&h01);
    r.y = *reinterpret_cast<unsigned*>(&h23);
    return r;
}

__device__ __forceinline__ void ldsm_x4(
    uint32_t& r0, uint32_t& r1, uint32_t& r2, uint32_t& r3, unsigned addr)
{
    asm volatile("ldmatrix.sync.aligned.m8n8.x4.shared.b16 {%0,%1,%2,%3}, [%4];"
                 : "=r"(r0), "=r"(r1), "=r"(r2), "=r"(r3) : "r"(addr));
}

__device__ __forceinline__ void mma_f16(
    float* d, uint32_t a0, uint32_t a1, uint32_t a2, uint32_t a3,
    uint32_t b0, uint32_t b1)
{
    asm volatile(
        "mma.sync.aligned.m16n8k16.row.col.f32.f16.f16.f32 "
        "{%0,%1,%2,%3}, {%4,%5,%6,%7}, {%8,%9}, {%0,%1,%2,%3};"
        : "+f"(d[0]), "+f"(d[1]), "+f"(d[2]), "+f"(d[3])
        : "r"(a0), "r"(a1), "r"(a2), "r"(a3), "r"(b0), "r"(b1));
}

// Packed f32x2 ops (stage2)
__device__ __forceinline__ unsigned long long add2(
    unsigned long long a, unsigned long long b)
{
    unsigned long long d;
    asm("add.rn.f32x2 %0, %1, %2;" : "=l"(d) : "l"(a), "l"(b));
    return d;
}
__device__ __forceinline__ unsigned long long ffma2(
    unsigned long long a, unsigned long long b, unsigned long long c)
{
    unsigned long long d;
    asm("fma.rn.f32x2 %0, %1, %2, %3;" : "=l"(d) : "l"(a), "l"(b), "l"(c));
    return d;
}
__device__ __forceinline__ unsigned long long relu2(unsigned long long x)
{
    unsigned long long r;
    asm("{\n\t.reg .f32 lo, hi;\n\t"
        "mov.b64 {lo, hi}, %1;\n\t"
        "max.f32 lo, lo, 0f00000000;\n\t"
        "max.f32 hi, hi, 0f00000000;\n\t"
        "mov.b64 %0, {lo, hi};\n\t}"
        : "=l"(r) : "l"(x));
    return r;
}
__device__ __forceinline__ float2 unpk2(unsigned long long v)
{
    float2 f;
    asm("mov.b64 {%0, %1}, %2;" : "=f"(f.x), "=f"(f.y) : "l"(v));
    return f;
}

// ---------------------------------------------------------------------------
// Stage 1: fp16 GEMM on mma.sync m16n8k16 (single pass, fp32 accumulate).
//   C[r][h] = sum_k X[r][k] * W[h][k]
// Block tile M=32, N=64; 8 warps = 2(m) x 4(n); warp tile 16x16.
// K chunked by 64 (one SW128 atom row: 64 fp16 = 128B), double-buffered,
// one sync per chunk: LDG(t+1) -> MMA(t) -> cvt+STS(t+1) -> sync.
// Grid (48, 2, 2) = 192 blocks.
// ---------------------------------------------------------------------------
#define AH_OFF    0
#define BH_OFF    4096
#define BUF_BYTES 12288
#define S1_SMEM   (2 * BUF_BYTES)   // 24576

__global__ __launch_bounds__(256) void stage1_kernel(
    const float* __restrict__ X0, const float* __restrict__ X1,
    const float* __restrict__ W1, const float* __restrict__ b1)
{
    extern __shared__ char smem[];
    const unsigned sbase = smem_u32(smem);

    const int mt = blockIdx.x;   // 0..47
    const int nt = blockIdx.y;   // 0..1
    const int z  = blockIdx.z;   // 0..1
    const int m0 = mt * 32;
    const int n0 = nt * 64;

    const float* __restrict__ X = z ? X1 : X0;
    const float* __restrict__ W = W1 + (size_t)z * DD;   // row stride 2*DD
    float* __restrict__ C = z ? g_hb : g_ha;

    const int tid  = threadIdx.x;
    const int wid  = tid >> 5;
    const int lane = tid & 31;
    const int wm   = wid & 1;    // m offset wm*16
    const int wn   = wid >> 1;   // n offset wn*16

    // Fill coords: A tile 32x64 = 512 float4 -> 2/thread;
    //              B tile 64x64 = 1024 float4 -> 4/thread.
    int arow[2], aq[2], brow[4], bq[4];
    #pragma unroll
    for (int i = 0; i < 2; i++) {
        const int flat = tid + i * 256;
        arow[i] = flat >> 4;  aq[i] = flat & 15;
    }
    #pragma unroll
    for (int i = 0; i < 4; i++) {
        const int flat = tid + i * 256;
        brow[i] = flat >> 4;  bq[i] = flat & 15;
    }

    // ldmatrix lane addressing
    const int a_r  = (lane & 15);
    const int a_ch = (lane >> 4);           // 0..1
    const int b_n  = (lane & 7) + ((lane >> 4) << 3);
    const int b_ch = (lane >> 3) & 1;

    float4 rA[2], rB[4];

    // ---- prologue: LDG chunk 0, cvt+STS into buf 0, sync ----
    #pragma unroll
    for (int i = 0; i < 2; i++)
        rA[i] = *reinterpret_cast<const float4*>(
            &X[(size_t)(m0 + arow[i]) * DD + aq[i] * 4]);
    #pragma unroll
    for (int i = 0; i < 4; i++)
        rB[i] = *reinterpret_cast<const float4*>(
            &W[(size_t)(n0 + brow[i]) * (2 * DD) + bq[i] * 4]);

    #pragma unroll
    for (int i = 0; i < 2; i++) {
        const unsigned so = sw128((unsigned)(arow[i] * 128 + aq[i] * 8));
        *reinterpret_cast<uint2*>(smem + AH_OFF + so) = cvt_h4(rA[i]);
    }
    #pragma unroll
    for (int i = 0; i < 4; i++) {
        const unsigned so = sw128((unsigned)(brow[i] * 128 + bq[i] * 8));
        *reinterpret_cast<uint2*>(smem + BH_OFF + so) = cvt_h4(rB[i]);
    }
    __syncthreads();

    float acc[2][4];
    #pragma unroll
    for (int ni = 0; ni < 2; ni++)
        #pragma unroll
        for (int r = 0; r < 4; r++) acc[ni][r] = 0.0f;

    #pragma unroll 1
    for (int t = 0; t < 8; t++) {
        const unsigned bufOff = (unsigned)((t & 1) * BUF_BYTES);

        // ---- LDG for chunk t+1 (latency hidden behind MMAs below) ----
        if (t < 7) {
            const int k0 = (t + 1) * 64;
            #pragma unroll
            for (int i = 0; i < 2; i++)
                rA[i] = *reinterpret_cast<const float4*>(
                    &X[(size_t)(m0 + arow[i]) * DD + k0 + aq[i] * 4]);
            #pragma unroll
            for (int i = 0; i < 4; i++)
                rB[i] = *reinterpret_cast<const float4*>(
                    &W[(size_t)(n0 + brow[i]) * (2 * DD) + k0 + bq[i] * 4]);
        }

        // ---- MMAs on buffer t ----
        const unsigned aH = sbase + bufOff + AH_OFF;
        const unsigned bH = sbase + bufOff + BH_OFF;

        #pragma unroll
        for (int ks = 0; ks < 4; ks++) {
            const unsigned kb = (unsigned)(ks * 32);

            uint32_t ah[4];
            {
                const unsigned off = sw128(
                    (unsigned)((wm * 16 + a_r) * 128) + kb + a_ch * 16);
                ldsm_x4(ah[0], ah[1], ah[2], ah[3], aH + off);
            }
            uint32_t bh[4];
            {
                const unsigned off = sw128(
                    (unsigned)((wn * 16 + b_n) * 128) + kb + b_ch * 16);
                ldsm_x4(bh[0], bh[1], bh[2], bh[3], bH + off);
            }

            #pragma unroll
            for (int ni = 0; ni < 2; ni++)
                mma_f16(acc[ni], ah[0], ah[1], ah[2], ah[3],
                        bh[2 * ni], bh[2 * ni + 1]);
        }

        // ---- cvt + STS chunk t+1 into the OTHER buffer, then one sync ----
        if (t < 7) {
            const unsigned nbuf = (unsigned)(((t + 1) & 1) * BUF_BYTES);
            #pragma unroll
            for (int i = 0; i < 2; i++) {
                const unsigned so = sw128((unsigned)(arow[i] * 128 + aq[i] * 8));
                *reinterpret_cast<uint2*>(smem + nbuf + AH_OFF + so) = cvt_h4(rA[i]);
            }
            #pragma unroll
            for (int i = 0; i < 4; i++) {
                const unsigned so = sw128((unsigned)(brow[i] * 128 + bq[i] * 8));
                *reinterpret_cast<uint2*>(smem + nbuf + BH_OFF + so) = cvt_h4(rB[i]);
            }
            __syncthreads();
        }
    }

    // ---- Epilogue: write D fragments (+ b1 for z=0) ----
    #pragma unroll
    for (int ni = 0; ni < 2; ni++) {
        const int row = m0 + wm * 16 + (lane >> 2);
        const int col = n0 + wn * 16 + ni * 8 + (lane & 3) * 2;
        float2 bias = make_float2(0.f, 0.f);
        if (z == 0)
            bias = *reinterpret_cast<const float2*>(&b1[col]);
        float2 o0, o1;
        o0.x = acc[ni][0] + bias.x;
        o0.y = acc[ni][1] + bias.y;
        o1.x = acc[ni][2] + bias.x;
        o1.y = acc[ni][3] + bias.y;
        *reinterpret_cast<float2*>(&C[(size_t)row * HIDN + col]) = o0;
        *reinterpret_cast<float2*>(&C[(size_t)(row + 8) * HIDN + col]) = o1;
    }
}

// ---------------------------------------------------------------------------
// Stage 2 (R8 measured-best variant):
// out[i,j,b,c] = sum_h relu(ha'[i,b,h]+hb[j,b,h])*W2[c,h]+b2[c]
// Grid (3,3,16): 32x32 (i,j) tile at fixed b, 256 threads, 2x2 per thread.
// Packed along h: add.rn.f32x2 + relu2 + per-channel fma.rn.f32x2 with
// (even-h, odd-h) split accumulators; horizontal add at the end.
// ---------------------------------------------------------------------------
#define TI 32
#define TJ 32
#define PADH 132  // 128+4 -> reduced bank conflicts, 16B aligned

__global__ __launch_bounds__(256) void stage2_kernel(
    const float* __restrict__ W2, const float* __restrict__ b2,
    float* __restrict__ out)
{
    __shared__ float sA[TI][PADH];
    __shared__ float sB[TJ][PADH];
    __shared__ float sW2[2 * HIDN];

    const int i0  = blockIdx.x * TI;
    const int j0  = blockIdx.y * TJ;
    const int b   = blockIdx.z;
    const int tid = threadIdx.x;

    #pragma unroll
    for (int i = 0; i < 4; i++) {
        const int q   = tid + i * 256;  // 0..1023
        const int row = q >> 5;         // 0..31
        const int hq  = q & 31;         // float4 index along h

        float4 va = *reinterpret_cast<const float4*>(
            &g_ha[((size_t)(i0 + row) * BB + b) * HIDN + hq * 4]);
        *reinterpret_cast<float4*>(&sA[row][hq * 4]) = va;

        float4 vb = *reinterpret_cast<const float4*>(
            &g_hb[((size_t)(j0 + row) * BB + b) * HIDN + hq * 4]);
        *reinterpret_cast<float4*>(&sB[row][hq * 4]) = vb;
    }
    if (tid < 64) {
        float4 w = *reinterpret_cast<const float4*>(&W2[tid * 4]);
        *reinterpret_cast<float4*>(&sW2[tid * 4]) = w;
    }
    __syncthreads();

    const int rg = tid >> 4;   // 0..15 -> i rows rg, rg+16
    const int cg = tid & 15;   // 0..15 -> j cols cg, cg+16

    // acc[ii][jj][c]: packed (even-h, odd-h) partial sums for channel c
    unsigned long long acc[2][2][2];
    #pragma unroll
    for (int ii = 0; ii < 2; ii++)
        #pragma unroll
        for (int jj = 0; jj < 2; jj++) {
            acc[ii][jj][0] = 0ull;
            acc[ii][jj][1] = 0ull;
        }

    #pragma unroll
    for (int hq = 0; hq < HIDN / 4; hq++) {
        ulonglong2 a0 = *reinterpret_cast<const ulonglong2*>(&sA[rg][hq * 4]);
        ulonglong2 a1 = *reinterpret_cast<const ulonglong2*>(&sA[rg + 16][hq * 4]);
        ulonglong2 q0 = *reinterpret_cast<const ulonglong2*>(&sB[cg][hq * 4]);
        ulonglong2 q1 = *reinterpret_cast<const ulonglong2*>(&sB[cg + 16][hq * 4]);
        ulonglong2 w0 = *reinterpret_cast<const ulonglong2*>(&sW2[hq * 4]);
        ulonglong2 w1 = *reinterpret_cast<const ulonglong2*>(&sW2[HIDN + hq * 4]);

        const unsigned long long av[2][2] = {{a0.x, a0.y}, {a1.x, a1.y}};
        const unsigned long long qv[2][2] = {{q0.x, q0.y}, {q1.x, q1.y}};
        const unsigned long long wv[2][2] = {{w0.x, w0.y}, {w1.x, w1.y}};

        #pragma unroll
        for (int hp = 0; hp < 2; hp++) {
            #pragma unroll
            for (int ii = 0; ii < 2; ii++)
                #pragma unroll
                for (int jj = 0; jj < 2; jj++) {
                    unsigned long long v = relu2(add2(av[ii][hp], qv[jj][hp]));
                    acc[ii][jj][0] = ffma2(v, wv[0][hp], acc[ii][jj][0]);
                    acc[ii][jj][1] = ffma2(v, wv[1][hp], acc[ii][jj][1]);
                }
        }
    }

    const float bb0 = b2[0];
    const float bb1 = b2[1];
    #pragma unroll
    for (int ii = 0; ii < 2; ii++)
        #pragma unroll
        for (int jj = 0; jj < 2; jj++) {
            const int i = i0 + rg + ii * 16;
            const int j = j0 + cg + jj * 16;
            const size_t idx = (((size_t)i * SS + j) * BB + b) * 2;
            float2 p0 = unpk2(acc[ii][jj][0]);
            float2 p1 = unpk2(acc[ii][jj][1]);
            float2 o;
            o.x = p0.x + p0.y + bb0;
            o.y = p1.x + p1.y + bb1;
            *reinterpret_cast<float2*>(&out[idx]) = o;
        }
}

// ---------------------------------------------------------------------------
// Inputs: embeds, umask, qmask, embeds_cmp, W1, b1, W2, b2
// ---------------------------------------------------------------------------
extern "C" void kernel_launch(void* const* d_in, const int* in_sizes, int n_in,
                              void* d_out, int out_size)
{
    const float* embeds     = (const float*)d_in[0];
    const float* embeds_cmp = (const float*)d_in[3];
    const float* W1         = (const float*)d_in[4];
    const float* b1         = (const float*)d_in[5];
    const float* W2         = (const float*)d_in[6];
    const float* b2         = (const float*)d_in[7];
    float* out = (float*)d_out;

    cudaFuncSetAttribute(stage1_kernel,
                         cudaFuncAttributeMaxDynamicSharedMemorySize, S1_SMEM);

    stage1_kernel<<<dim3(48, 2, 2), 256, S1_SMEM>>>(embeds, embeds_cmp, W1, b1);
    stage2_kernel<<<dim3(3, 3, 16), 256>>>(W2, b2, out);
}